// round 14
// baseline (speedup 1.0000x reference)
#include <cuda_runtime.h>
#include <cuda_fp16.h>
#include <cstdint>

// Problem constants
#define SQ   2048
#define BB   2
#define EE   1024
#define HH   16
#define DD   64
#define MM   (SQ * BB)
#define SHIFT 4.0f
#define NWALL4 (((3 * EE + EE) * EE) / 4)   // w + wo float4 count = 1048576

// ---------------------------------------------------------------------------
// Scratch (device globals — no allocation allowed)
// ---------------------------------------------------------------------------
__device__ __half g_w16[3u * EE * EE];          // in_proj_w fp16
__device__ __half g_wo16[(size_t)EE * EE];      // out_proj_w fp16
__device__ __half g_q16[BB * HH * SQ * DD];     // [B,H,S,D] (q pre-scaled 1/8)
__device__ __half g_k16[BB * HH * SQ * DD];
__device__ __half g_v16t[BB * HH * DD * SQ];    // [B,H,D,S] (transposed)
__device__ __half g_c16[(size_t)MM * EE];       // ctx [S,B,E] fp16

// ---------------------------------------------------------------------------
// PTX helpers (sm_80+ portable — harness targets plain sm_103)
// ---------------------------------------------------------------------------
__device__ __forceinline__ uint32_t smem_u32(const void* p) {
    uint32_t a;
    asm("{ .reg .u64 t; cvta.to.shared.u64 t, %1; cvt.u32.u64 %0, t; }"
        : "=r"(a) : "l"(p));
    return a;
}

#define CP_ASYNC16(saddr, gaddr) \
    asm volatile("cp.async.cg.shared.global [%0], [%1], 16;" \
                 :: "r"(saddr), "l"(gaddr) : "memory")
#define CP_COMMIT() asm volatile("cp.async.commit_group;" ::: "memory")
#define CP_WAIT(n)  asm volatile("cp.async.wait_group %0;" :: "n"(n) : "memory")

__device__ __forceinline__ void ldsm_x4(uint32_t* r, uint32_t addr) {
    asm volatile("ldmatrix.sync.aligned.m8n8.x4.shared.b16 {%0,%1,%2,%3}, [%4];"
                 : "=r"(r[0]), "=r"(r[1]), "=r"(r[2]), "=r"(r[3]) : "r"(addr));
}

__device__ __forceinline__ void mma_f16(float* d, const uint32_t* a, const uint32_t* b) {
    asm volatile("mma.sync.aligned.m16n8k16.row.col.f32.f16.f16.f32 "
                 "{%0,%1,%2,%3}, {%4,%5,%6,%7}, {%8,%9}, {%0,%1,%2,%3};"
                 : "+f"(d[0]), "+f"(d[1]), "+f"(d[2]), "+f"(d[3])
                 : "r"(a[0]), "r"(a[1]), "r"(a[2]), "r"(a[3]), "r"(b[0]), "r"(b[1]));
}

__device__ __forceinline__ uint32_t pkh(__half lo, __half hi) {
    return ((uint32_t)__half_as_ushort(hi) << 16) | (uint32_t)__half_as_ushort(lo);
}
__device__ __forceinline__ uint32_t cvt2(float a, float b) {
    return pkh(__float2half_rn(a), __float2half_rn(b));
}

// ---------------------------------------------------------------------------
// Weights-only fp32 -> fp16 conversion (w then wo, contiguous), MLP=4.
// ---------------------------------------------------------------------------
__global__ __launch_bounds__(256) void cvt_w_kernel(
    const float4* __restrict__ w, const float4* __restrict__ wo)
{
    const int blk0 = blockIdx.x * 1024;
    const int NW4 = (3 * EE * EE) / 4;
    const float4* __restrict__ src;
    uint2* __restrict__ dst;
    if (blk0 < NW4) { src = w + blk0;          dst = (uint2*)g_w16 + blk0; }
    else            { src = wo + (blk0 - NW4); dst = (uint2*)g_wo16 + (blk0 - NW4); }
    const int tid = threadIdx.x;
    float4 vv[4];
#pragma unroll
    for (int u = 0; u < 4; u++)
        vv[u] = src[tid + u * 256];
#pragma unroll
    for (int u = 0; u < 4; u++) {
        uint2 o;
        o.x = cvt2(vv[u].x, vv[u].y);
        o.y = cvt2(vv[u].z, vv[u].w);
        dst[tid + u * 256] = o;
    }
}

// ---------------------------------------------------------------------------
// QKV projection, fp16 single-pass with FUSED fp32->fp16 conversion of A.
// A streams in as fp32 (cp.async) into a staging buffer; after the wait,
// threads convert smem32 -> smem16, then ldmatrix as usual. W pre-converted.
// Tile 128x128, BK=32, 32 stages, 8 warps (2M x 4N of 64x32), 2 blocks/SM.
// smem (bytes): A32[2] 0..36864 (rows 144B) | A16[2] 36864..57344 (rows 80B)
//             | W16[2] 57344..77824 (rows 80B).
// FIX vs r12: a_lane / b_lane now include the smem base (sb) — the r12 NaN
// came from ldmatrix consuming offsets without the base.
// ---------------------------------------------------------------------------
__global__ __launch_bounds__(256, 2) void qkv_gemm_kernel(
    const float* __restrict__ a0p, const float* __restrict__ a1p,
    const float* __restrict__ a2p, const float* __restrict__ bias)
{
    extern __shared__ __align__(16) char smQ[];
    float* smf = (float*)smQ;
    const uint32_t sb = smem_u32(smQ);
    const int tid  = threadIdx.x;
    const int wid  = tid >> 5;
    const int lane = tid & 31;
    const int g    = lane >> 2;
    const int tg   = lane & 3;
    const int m0 = blockIdx.x * 128;
    const int n0 = blockIdx.y * 128;

    const int which = n0 >> 10;
    const float* __restrict__ A = (which == 0) ? a0p : (which == 1) ? a1p : a2p;
    const __half* __restrict__ W = g_w16;

    const int warp_m = (wid & 1) * 64;
    const int warp_n = (wid >> 1) * 32;

    const int a_row   = (lane & 7) + ((lane >> 3) & 1) * 8;
    const int a_chunk = lane >> 4;
    const int b_row   = lane & 7;
    const int b_sel   = lane >> 4;
    const int b_chunk = (lane >> 3) & 1;
    const uint32_t a_lane = sb + 36864u + (uint32_t)((warp_m + a_row) * 80 + a_chunk * 16);
    const uint32_t b_lane = sb + 57344u + (uint32_t)((warp_n + b_sel * 8 + b_row) * 80 + b_chunk * 16);

    // cvt-step addressing: thread handles row r = tid>>1, 16-float half h
    const int cv_row = tid >> 1;
    const int cv_h   = tid & 1;

    float acc[4][4][4];
#pragma unroll
    for (int mi = 0; mi < 4; mi++)
#pragma unroll
        for (int ni = 0; ni < 4; ni++)
#pragma unroll
            for (int r = 0; r < 4; r++) acc[mi][ni][r] = 0.0f;

    auto issue_stage = [&](int s) {
        const int k0 = s * 32;
        const uint32_t a32b = sb + (uint32_t)(s & 1) * 18432u;
        const uint32_t w16b = sb + 57344u + (uint32_t)(s & 1) * 10240u;
        // A fp32: 128 rows x 128B data (144B rows) = 1024 chunks, 4/thread
#pragma unroll
        for (int u = 0; u < 4; u++) {
            int ch = tid + u * 256;
            int row = ch >> 3, c = ch & 7;
            CP_ASYNC16(a32b + (uint32_t)row * 144u + (uint32_t)c * 16u,
                       A + (size_t)(m0 + row) * EE + k0 + c * 4);
        }
        // W fp16: 128 rows x 64B data (80B rows) = 512 chunks, 2/thread
#pragma unroll
        for (int u = 0; u < 2; u++) {
            int ch = tid + u * 256;
            int row = ch >> 2, c = ch & 3;
            CP_ASYNC16(w16b + (uint32_t)row * 80u + (uint32_t)c * 16u,
                       W + (size_t)(n0 + row) * EE + k0 + c * 8);
        }
        CP_COMMIT();
    };

    issue_stage(0);

    for (int s = 0; s < 32; s++) {
        if (s + 1 < 32) { issue_stage(s + 1); CP_WAIT(1); }
        else            { CP_WAIT(0); }
        __syncthreads();

        // --- fused cvt: A32(s&1) -> A16(s&1) ---
        {
            const float* a32 = smf + (s & 1) * 4608 + cv_row * 36 + cv_h * 16;
            float4 f0 = *(const float4*)(a32 + 0);
            float4 f1 = *(const float4*)(a32 + 4);
            float4 f2 = *(const float4*)(a32 + 8);
            float4 f3 = *(const float4*)(a32 + 12);
            uint4 o0, o1;
            o0.x = cvt2(f0.x, f0.y); o0.y = cvt2(f0.z, f0.w);
            o0.z = cvt2(f1.x, f1.y); o0.w = cvt2(f1.z, f1.w);
            o1.x = cvt2(f2.x, f2.y); o1.y = cvt2(f2.z, f2.w);
            o1.z = cvt2(f3.x, f3.y); o1.w = cvt2(f3.z, f3.w);
            char* a16 = smQ + 36864 + (s & 1) * 10240 + cv_row * 80 + cv_h * 32;
            *(uint4*)(a16 + 0)  = o0;
            *(uint4*)(a16 + 16) = o1;
        }
        __syncthreads();

        const uint32_t bo = (uint32_t)(s & 1) * 10240u;
#pragma unroll
        for (int ks = 0; ks < 2; ks++) {
            uint32_t bf[4][2];
#pragma unroll
            for (int np = 0; np < 2; np++) {
                uint32_t r[4];
                ldsm_x4(r, b_lane + bo + (uint32_t)np * 1280u + ks * 32);
                bf[np * 2][0] = r[0];     bf[np * 2][1] = r[1];
                bf[np * 2 + 1][0] = r[2]; bf[np * 2 + 1][1] = r[3];
            }
#pragma unroll
            for (int mi = 0; mi < 4; mi++) {
                uint32_t af[4];
                ldsm_x4(af, a_lane + bo + (uint32_t)mi * 1280u + ks * 32);
#pragma unroll
                for (int ni = 0; ni < 4; ni++)
                    mma_f16(acc[mi][ni], af, bf[ni]);
            }
        }
        __syncthreads();
    }

    const float scale = (which == 0) ? 0.125f : 1.0f;
    __half* dst = (which == 0) ? g_q16 : g_k16;

#pragma unroll
    for (int mi = 0; mi < 4; mi++) {
        const int m1 = m0 + warp_m + mi * 16 + g;
        const int m2 = m1 + 8;
        const int s1 = m1 >> 1, b1 = m1 & 1;
        const int s2 = m2 >> 1, b2 = m2 & 1;
#pragma unroll
        for (int ni = 0; ni < 4; ni++) {
            const int n = n0 + warp_n + ni * 8 + tg * 2;
            const float bb0 = bias[n], bb1 = bias[n + 1];
            __half v00 = __float2half_rn((acc[mi][ni][0] + bb0) * scale);
            __half v01 = __float2half_rn((acc[mi][ni][1] + bb1) * scale);
            __half v10 = __float2half_rn((acc[mi][ni][2] + bb0) * scale);
            __half v11 = __float2half_rn((acc[mi][ni][3] + bb1) * scale);
            const int nl = n & 1023;
            const int h  = nl >> 6;
            const int d  = nl & 63;
            if (which < 2) {
                size_t base1 = (((size_t)(b1 * HH + h) * SQ + s1) * DD) + d;
                size_t base2 = (((size_t)(b2 * HH + h) * SQ + s2) * DD) + d;
                *(uint32_t*)&dst[base1] = pkh(v00, v01);
                *(uint32_t*)&dst[base2] = pkh(v10, v11);
            } else {
                size_t r1 = ((size_t)(b1 * HH + h) * DD + d) * SQ;
                size_t r2 = ((size_t)(b2 * HH + h) * DD + d) * SQ;
                g_v16t[r1 + s1]      = v00;
                g_v16t[r1 + SQ + s1] = v01;
                g_v16t[r2 + s2]      = v10;
                g_v16t[r2 + SQ + s2] = v11;
            }
        }
    }
}

// ---------------------------------------------------------------------------
// Banded flash attention, fp16, register-resident P, double-buffered K/V.
// (unchanged from r10)
// ---------------------------------------------------------------------------
__global__ __launch_bounds__(256, 2) void attn_kernel()
{
    extern __shared__ __align__(16) char smA[];
    const uint32_t sb = smem_u32(smA);

    const int t   = blockIdx.x;
    const int bh  = blockIdx.y;
    const int tid = threadIdx.x;
    const int w    = tid >> 5;
    const int lane = tid & 31;
    const int g    = lane >> 2;
    const int tg   = lane & 3;

    const int a_row   = (lane & 7) + ((lane >> 3) & 1) * 8;
    const int a_chunk = lane >> 4;
    const int b_row   = lane & 7;
    const int b_sel   = lane >> 4;
    const int b_chunk = (lane >> 3) & 1;

    const uint32_t q_lane = sb + (uint32_t)((w * 16 + a_row) * 144 + a_chunk * 16);
    const uint32_t k_lane = sb + 18432u + (uint32_t)((b_sel * 8 + b_row) * 144 + b_chunk * 16);
    const uint32_t v_lane = sb + 36864u + (uint32_t)((b_sel * 8 + b_row) * 272 + b_chunk * 16);

    auto issue_kv = [&](int kt, int buf) {
        const __half* kp = g_k16 + ((size_t)bh * SQ + kt * 128) * DD;
        const __half* vp = g_v16t + (size_t)bh * DD * SQ + kt * 128;
        const uint32_t kb = sb + 18432u + (uint32_t)buf * 35840u;
        const uint32_t vb = sb + 36864u + (uint32_t)buf * 35840u;
#pragma unroll
        for (int u = 0; u < 8; u++) {
            int ch = tid + u * 256;
            if (ch < 1024) {
                int kr = ch >> 3, kc = ch & 7;
                CP_ASYNC16(kb + (uint32_t)kr * 144u + (uint32_t)kc * 16u,
                           kp + kr * DD + kc * 8);
            } else {
                int vi = ch - 1024;
                int vr = vi >> 4, vc = vi & 15;
                CP_ASYNC16(vb + (uint32_t)vr * 272u + (uint32_t)vc * 16u,
                           vp + (size_t)vr * SQ + vc * 8);
            }
        }
        CP_COMMIT();
    };

    const int kt0 = (t > 0) ? t - 1 : t;
    const int kt1 = (t < SQ / 128 - 1) ? t + 1 : t;
    const int nkt = kt1 - kt0 + 1;

    {
        const __half* qp = g_q16 + ((size_t)bh * SQ + t * 128) * DD;
#pragma unroll
        for (int u = 0; u < 4; u++) {
            int ch = tid + u * 256;
            int row = ch >> 3, c = ch & 7;
            CP_ASYNC16(sb + (uint32_t)row * 144u + (uint32_t)c * 16u, qp + row * DD + c * 8);
        }
        CP_COMMIT();
    }
    issue_kv(kt0, 0);

    float l0 = 0.f, l1 = 0.f;
    float O[8][4];
#pragma unroll
    for (int nf = 0; nf < 8; nf++)
#pragma unroll
        for (int r = 0; r < 4; r++) O[nf][r] = 0.f;

    uint32_t qf[4][4];
    uint32_t Pf[8][4];
    bool qloaded = false;

#pragma unroll 1
    for (int it = 0; it < nkt; it++) {
        const int kt = kt0 + it;
        if (it + 1 < nkt) { issue_kv(kt + 1, (it + 1) & 1); CP_WAIT(1); }
        else              { CP_WAIT(0); }
        __syncthreads();

        if (!qloaded) {
            qloaded = true;
#pragma unroll
            for (int ks = 0; ks < 4; ks++)
                ldsm_x4(qf[ks], q_lane + ks * 32);
        }

        const uint32_t bufo = (uint32_t)(it & 1) * 35840u;
        const int dt = kt - t;
        const int niLo = (dt < 0) ? 2 * w : 0;
        const int niHi = (dt > 0) ? 2 * w + 2 : 16;
        const int r0 = w * 16 + g;
        const int r1 = r0 + 8;

#pragma unroll
        for (int ni = 0; ni < 16; ni += 2) {
            if (ni >= niLo && ni < niHi) {
                float c0[4] = {0.f, 0.f, 0.f, 0.f};
                float c1[4] = {0.f, 0.f, 0.f, 0.f};
                const uint32_t kb = k_lane + bufo + (uint32_t)ni * 1152u;
#pragma unroll
                for (int ks = 0; ks < 4; ks++) {
                    uint32_t r[4];
                    ldsm_x4(r, kb + ks * 32);
                    mma_f16(c0, qf[ks], r);
                    mma_f16(c1, qf[ks], r + 2);
                }
#pragma unroll
                for (int q2 = 0; q2 < 2; q2++) {
                    float* c = (q2 == 0) ? c0 : c1;
                    const int col0 = (ni + q2) * 8 + 2 * tg;
                    float p0, p1, p2, p3;
                    if (dt < 0) {
                        p0 = (col0     >= r0) ? __expf(c[0] - SHIFT) : 0.f;
                        p1 = (col0 + 1 >= r0) ? __expf(c[1] - SHIFT) : 0.f;
                        p2 = (col0     >= r1) ? __expf(c[2] - SHIFT) : 0.f;
                        p3 = (col0 + 1 >= r1) ? __expf(c[3] - SHIFT) : 0.f;
                    } else if (dt > 0) {
                        p0 = (col0     < r0) ? __expf(c[0] - SHIFT) : 0.f;
                        p1 = (col0 + 1 < r0) ? __expf(c[1] - SHIFT) : 0.f;
                        p2 = (col0     < r1) ? __expf(c[2] - SHIFT) : 0.f;
                        p3 = (col0 + 1 < r1) ? __expf(c[3] - SHIFT) : 0.f;
                    } else {
                        p0 = __expf(c[0] - SHIFT); p1 = __expf(c[1] - SHIFT);
                        p2 = __expf(c[2] - SHIFT); p3 = __expf(c[3] - SHIFT);
                    }
                    l0 += p0 + p1;
                    l1 += p2 + p3;
                    const int ck = (ni + q2) >> 1;
                    if (((ni + q2) & 1) == 0) {
                        Pf[ck][0] = cvt2(p0, p1);
                        Pf[ck][1] = cvt2(p2, p3);
                    } else {
                        Pf[ck][2] = cvt2(p0, p1);
                        Pf[ck][3] = cvt2(p2, p3);
                    }
                }
            }
        }

        const int ksLo = (dt < 0) ? w : 0;
        const int ksHi = (dt > 0) ? w + 1 : 8;
#pragma unroll
        for (int ks = 0; ks < 8; ks++) {
            if (ks >= ksLo && ks < ksHi) {
#pragma unroll
                for (int nf = 0; nf < 8; nf += 2) {
                    uint32_t v[4];
                    ldsm_x4(v, v_lane + bufo + (uint32_t)nf * 2176u + ks * 32);
                    mma_f16(O[nf],     Pf[ks], v);
                    mma_f16(O[nf + 1], Pf[ks], v + 2);
                }
            }
        }
        if (it + 1 < nkt) __syncthreads();
    }

    l0 += __shfl_xor_sync(0xffffffff, l0, 1);
    l0 += __shfl_xor_sync(0xffffffff, l0, 2);
    l1 += __shfl_xor_sync(0xffffffff, l1, 1);
    l1 += __shfl_xor_sync(0xffffffff, l1, 2);
    const float inv0 = 1.0f / l0;
    const float inv1 = 1.0f / l1;

    const int b_ = bh >> 4;
    const int h_ = bh & 15;
    const int i0 = t * 128 + w * 16 + g;
    const int i1 = i0 + 8;
#pragma unroll
    for (int nf = 0; nf < 8; nf++) {
        const int d = h_ * 64 + nf * 8 + 2 * tg;
        size_t e0 = ((size_t)i0 * BB + b_) * EE + d;
        size_t e1 = ((size_t)i1 * BB + b_) * EE + d;
        *(uint32_t*)&g_c16[e0] = cvt2(O[nf][0] * inv0, O[nf][1] * inv0);
        *(uint32_t*)&g_c16[e1] = cvt2(O[nf][2] * inv1, O[nf][3] * inv1);
    }
}

// ---------------------------------------------------------------------------
// Output projection, fp16 single-pass (r10 256-thread, 128x128 config).
// ---------------------------------------------------------------------------
__global__ __launch_bounds__(256, 2) void outproj_kernel(
    const float* __restrict__ bias, float* __restrict__ outp)
{
    extern __shared__ __align__(16) char smB[];
    const uint32_t sb = smem_u32(smB);
    const int tid  = threadIdx.x;
    const int wid  = tid >> 5;
    const int lane = tid & 31;
    const int g    = lane >> 2;
    const int tg   = lane & 3;
    const int m0 = blockIdx.x * 128;
    const int n0 = blockIdx.y * 128;

    const int warp_m = (wid & 1) * 64;
    const int warp_n = (wid >> 1) * 32;

    const int a_row   = (lane & 7) + ((lane >> 3) & 1) * 8;
    const int a_chunk = lane >> 4;
    const int b_row   = lane & 7;
    const int b_sel   = lane >> 4;
    const int b_chunk = (lane >> 3) & 1;

    const uint32_t a_lane = (uint32_t)((warp_m + a_row) * 144 + a_chunk * 16);
    const uint32_t b_lane = 18432u + (uint32_t)((warp_n + b_sel * 8 + b_row) * 144 + b_chunk * 16);

    float acc[4][4][4];
#pragma unroll
    for (int mi = 0; mi < 4; mi++)
#pragma unroll
        for (int ni = 0; ni < 4; ni++)
#pragma unroll
            for (int r = 0; r < 4; r++) acc[mi][ni][r] = 0.0f;

    auto issue_stage = [&](int s) {
        const int k0 = s * 64;
        const uint32_t base = sb + (uint32_t)(s & 1) * 36864u;
#pragma unroll
        for (int u = 0; u < 8; u++) {
            int ch  = tid + u * 256;
            int arr = ch >> 10;
            int rem = ch & 1023;
            int row = rem >> 3;
            int c   = rem & 7;
            uint32_t so = (uint32_t)arr * 18432u + (uint32_t)row * 144u + (uint32_t)c * 16u;
            const __half* gp = (arr == 0)
                ? g_c16  + (size_t)(m0 + row) * EE + k0 + c * 8
                : g_wo16 + (size_t)(n0 + row) * EE + k0 + c * 8;
            CP_ASYNC16(base + so, gp);
        }
        CP_COMMIT();
    };

    issue_stage(0);

    for (int s = 0; s < 16; s++) {
        if (s + 1 < 16) { issue_stage(s + 1); CP_WAIT(1); }
        else            { CP_WAIT(0); }
        __syncthreads();

        const uint32_t stb = sb + (uint32_t)(s & 1) * 36864u;
#pragma unroll
        for (int ks = 0; ks < 4; ks++) {
            uint32_t bf[4][2];
#pragma unroll
            for (int np = 0; np < 2; np++) {
                uint32_t r[4];
                ldsm_x4(r, stb + b_lane + (uint32_t)np * 2304u + ks * 32);
                bf[np * 2][0] = r[0];     bf[np * 2][1] = r[1];
                bf[np * 2 + 1][0] = r[2]; bf[np * 2 + 1][1] = r[3];
            }
#pragma unroll
            for (int mi = 0; mi < 4; mi++) {
                uint32_t af[4];
                ldsm_x4(af, stb + a_lane + (uint32_t)mi * 2304u + ks * 32);
#pragma unroll
                for (int ni = 0; ni < 4; ni++)
                    mma_f16(acc[mi][ni], af, bf[ni]);
            }
        }
        __syncthreads();
    }

#pragma unroll
    for (int mi = 0; mi < 4; mi++) {
        const int m1 = m0 + warp_m + mi * 16 + g;
        const int m2 = m1 + 8;
#pragma unroll
        for (int ni = 0; ni < 4; ni++) {
            const int n = n0 + warp_n + ni * 8 + tg * 2;
            const float b0 = bias[n], b1 = bias[n + 1];
            *(float2*)&outp[(size_t)m1 * EE + n] =
                make_float2(acc[mi][ni][0] + b0, acc[mi][ni][1] + b1);
            *(float2*)&outp[(size_t)m2 * EE + n] =
                make_float2(acc[mi][ni][2] + b0, acc[mi][ni][3] + b1);
        }
    }
}

// ---------------------------------------------------------------------------
extern "C" void kernel_launch(void* const* d_in, const int* in_sizes, int n_in,
                              void* d_out, int out_size)
{
    const float* q_in  = (const float*)d_in[0];
    const float* k_in  = (const float*)d_in[1];
    const float* v_in  = (const float*)d_in[2];
    const float* w_in  = (const float*)d_in[3];
    const float* b_in  = (const float*)d_in[4];
    const float* w_out = (const float*)d_in[5];
    const float* b_out = (const float*)d_in[6];
    float* out = (float*)d_out;

    // Weights-only conversion (w + wo)
    cvt_w_kernel<<<NWALL4 / 1024, 256>>>((const float4*)w_in, (const float4*)w_out);

    // QKV projection with fused activation conversion, grid 32 x 24
    const int qkv_smem = 77824;
    cudaFuncSetAttribute(qkv_gemm_kernel, cudaFuncAttributeMaxDynamicSharedMemorySize, qkv_smem);
    qkv_gemm_kernel<<<dim3(MM / 128, (3 * EE) / 128), 256, qkv_smem>>>(
        q_in, k_in, v_in, b_in);

    // Banded attention (register-P fp16, double-buffered K/V)
    const int attn_smem = 90112;
    cudaFuncSetAttribute(attn_kernel, cudaFuncAttributeMaxDynamicSharedMemorySize, attn_smem);
    attn_kernel<<<dim3(SQ / 128, BB * HH), 256, attn_smem>>>();

    // Output projection (fp16 single-pass), grid 32 x 8
    const int op_smem = 73728;
    cudaFuncSetAttribute(outproj_kernel, cudaFuncAttributeMaxDynamicSharedMemorySize, op_smem);
    outproj_kernel<<<dim3(MM / 128, EE / 128), 256, op_smem>>>(b_out, out);
}

// round 15
// speedup vs baseline: 1.2277x; 1.2277x over previous
#include <cuda_runtime.h>
#include <cuda_fp16.h>
#include <cstdint>

// Problem constants
#define SQ   2048
#define BB   2
#define EE   1024
#define HH   16
#define DD   64
#define MM   (SQ * BB)
#define SHIFT 4.0f
#define NWALL4 (((3 * EE + EE) * EE) / 4)   // w + wo float4 count = 1048576

// ---------------------------------------------------------------------------
// Scratch (device globals — no allocation allowed)
// ---------------------------------------------------------------------------
__device__ __half g_w16[3u * EE * EE];          // in_proj_w fp16
__device__ __half g_wo16[(size_t)EE * EE];      // out_proj_w fp16
__device__ __half g_q16[BB * HH * SQ * DD];     // [B,H,S,D] (q pre-scaled 1/8)
__device__ __half g_k16[BB * HH * SQ * DD];
__device__ __half g_v16t[BB * HH * DD * SQ];    // [B,H,D,S] (transposed)
__device__ __half g_c16[(size_t)MM * EE];       // ctx [S,B,E] fp16

// ---------------------------------------------------------------------------
// PTX helpers (sm_80+ portable — harness targets plain sm_103)
// ---------------------------------------------------------------------------
__device__ __forceinline__ uint32_t smem_u32(const void* p) {
    uint32_t a;
    asm("{ .reg .u64 t; cvta.to.shared.u64 t, %1; cvt.u32.u64 %0, t; }"
        : "=r"(a) : "l"(p));
    return a;
}

#define CP_ASYNC16(saddr, gaddr) \
    asm volatile("cp.async.cg.shared.global [%0], [%1], 16;" \
                 :: "r"(saddr), "l"(gaddr) : "memory")
#define CP_COMMIT() asm volatile("cp.async.commit_group;" ::: "memory")
#define CP_WAIT(n)  asm volatile("cp.async.wait_group %0;" :: "n"(n) : "memory")

__device__ __forceinline__ void ldsm_x4(uint32_t* r, uint32_t addr) {
    asm volatile("ldmatrix.sync.aligned.m8n8.x4.shared.b16 {%0,%1,%2,%3}, [%4];"
                 : "=r"(r[0]), "=r"(r[1]), "=r"(r[2]), "=r"(r[3]) : "r"(addr));
}

__device__ __forceinline__ void mma_f16(float* d, const uint32_t* a, const uint32_t* b) {
    asm volatile("mma.sync.aligned.m16n8k16.row.col.f32.f16.f16.f32 "
                 "{%0,%1,%2,%3}, {%4,%5,%6,%7}, {%8,%9}, {%0,%1,%2,%3};"
                 : "+f"(d[0]), "+f"(d[1]), "+f"(d[2]), "+f"(d[3])
                 : "r"(a[0]), "r"(a[1]), "r"(a[2]), "r"(a[3]), "r"(b[0]), "r"(b[1]));
}

__device__ __forceinline__ uint32_t pkh(__half lo, __half hi) {
    return ((uint32_t)__half_as_ushort(hi) << 16) | (uint32_t)__half_as_ushort(lo);
}
__device__ __forceinline__ uint32_t cvt2(float a, float b) {
    return pkh(__float2half_rn(a), __float2half_rn(b));
}

// ---------------------------------------------------------------------------
// Weights-only fp32 -> fp16 conversion (w then wo, contiguous), MLP=4.
// ---------------------------------------------------------------------------
__global__ __launch_bounds__(256) void cvt_w_kernel(
    const float4* __restrict__ w, const float4* __restrict__ wo)
{
    const int blk0 = blockIdx.x * 1024;
    const int NW4 = (3 * EE * EE) / 4;
    const float4* __restrict__ src;
    uint2* __restrict__ dst;
    if (blk0 < NW4) { src = w + blk0;          dst = (uint2*)g_w16 + blk0; }
    else            { src = wo + (blk0 - NW4); dst = (uint2*)g_wo16 + (blk0 - NW4); }
    const int tid = threadIdx.x;
    float4 vv[4];
#pragma unroll
    for (int u = 0; u < 4; u++)
        vv[u] = src[tid + u * 256];
#pragma unroll
    for (int u = 0; u < 4; u++) {
        uint2 o;
        o.x = cvt2(vv[u].x, vv[u].y);
        o.y = cvt2(vv[u].z, vv[u].w);
        dst[tid + u * 256] = o;
    }
}

// ---------------------------------------------------------------------------
// QKV projection, fp16 single-pass, A converted in-register on the fly.
// A: fp32 LDG.128 prefetch (one stage ahead) -> cvt in regs -> STS fp16 into
//    the standard 144B-row tile. W: fp16 cp.async (pre-converted).
// Tile 128x128, BK=64, 16 stages, 8 warps (2M x 4N of 64x32), 2 blocks/SM.
// smem (bytes): A16[2] 0..36864 | W16[2] 36864..73728 (both 144B rows).
// Sync structure identical to r10 (2 syncthreads/stage).
// ---------------------------------------------------------------------------
__global__ __launch_bounds__(256, 2) void qkv_gemm_kernel(
    const float* __restrict__ a0p, const float* __restrict__ a1p,
    const float* __restrict__ a2p, const float* __restrict__ bias)
{
    extern __shared__ __align__(16) char smQ[];
    const uint32_t sb = smem_u32(smQ);
    const int tid  = threadIdx.x;
    const int wid  = tid >> 5;
    const int lane = tid & 31;
    const int g    = lane >> 2;
    const int tg   = lane & 3;
    const int m0 = blockIdx.x * 128;
    const int n0 = blockIdx.y * 128;

    const int which = n0 >> 10;
    const float* __restrict__ A = (which == 0) ? a0p : (which == 1) ? a1p : a2p;
    const __half* __restrict__ W = g_w16;

    const int warp_m = (wid & 1) * 64;
    const int warp_n = (wid >> 1) * 32;

    const int a_row   = (lane & 7) + ((lane >> 3) & 1) * 8;
    const int a_chunk = lane >> 4;
    const int b_row   = lane & 7;
    const int b_sel   = lane >> 4;
    const int b_chunk = (lane >> 3) & 1;
    const uint32_t a_lane = sb + (uint32_t)((warp_m + a_row) * 144 + a_chunk * 16);
    const uint32_t b_lane = sb + 36864u + (uint32_t)((warp_n + b_sel * 8 + b_row) * 144 + b_chunk * 16);

    // A LDG/STS mapping: 2048 float4 per stage (128 rows x 16 float4), 8/thread
    const int ld_row = tid >> 1;                 // base row pairing: ch = tid + u*256
    (void)ld_row;

    float acc[4][4][4];
#pragma unroll
    for (int mi = 0; mi < 4; mi++)
#pragma unroll
        for (int ni = 0; ni < 4; ni++)
#pragma unroll
            for (int r = 0; r < 4; r++) acc[mi][ni][r] = 0.0f;

    float4 ar[8];
    auto ldgA = [&](int s) {
        const int k0 = s * 64;
#pragma unroll
        for (int u = 0; u < 8; u++) {
            int ch = tid + u * 256;              // 0..2047
            int row = ch >> 4, c4 = ch & 15;
            ar[u] = *(const float4*)(A + (size_t)(m0 + row) * EE + k0 + c4 * 4);
        }
    };
    auto stsA = [&](int s) {
        char* buf = smQ + (s & 1) * 18432;
#pragma unroll
        for (int u = 0; u < 8; u++) {
            int ch = tid + u * 256;
            int row = ch >> 4, c4 = ch & 15;
            uint2 o;
            o.x = cvt2(ar[u].x, ar[u].y);
            o.y = cvt2(ar[u].z, ar[u].w);
            *(uint2*)(buf + row * 144 + c4 * 8) = o;
        }
    };
    auto issueW = [&](int s) {
        const int k0 = s * 64;
        const uint32_t base = sb + 36864u + (uint32_t)(s & 1) * 18432u;
#pragma unroll
        for (int u = 0; u < 4; u++) {
            int ch = tid + u * 256;              // 0..1023
            int row = ch >> 3, c = ch & 7;
            CP_ASYNC16(base + (uint32_t)row * 144u + (uint32_t)c * 16u,
                       W + (size_t)(n0 + row) * EE + k0 + c * 8);
        }
        CP_COMMIT();
    };

    // Prologue
    ldgA(0);
    stsA(0);
    issueW(0);
    ldgA(1);

    for (int s = 0; s < 16; s++) {
        if (s + 1 < 16) { issueW(s + 1); CP_WAIT(1); }
        else            { CP_WAIT(0); }
        __syncthreads();   // A16(s) STS + W(s) cp.async visible

        const uint32_t ab = a_lane + (uint32_t)(s & 1) * 18432u;
        const uint32_t bb = b_lane + (uint32_t)(s & 1) * 18432u;
#pragma unroll
        for (int ks = 0; ks < 4; ks++) {
            uint32_t bf[4][2];
#pragma unroll
            for (int np = 0; np < 2; np++) {
                uint32_t r[4];
                ldsm_x4(r, bb + (uint32_t)np * 2304u + ks * 32);
                bf[np * 2][0] = r[0];     bf[np * 2][1] = r[1];
                bf[np * 2 + 1][0] = r[2]; bf[np * 2 + 1][1] = r[3];
            }
#pragma unroll
            for (int mi = 0; mi < 4; mi++) {
                uint32_t af[4];
                ldsm_x4(af, ab + (uint32_t)mi * 2304u + ks * 32);
#pragma unroll
                for (int ni = 0; ni < 4; ni++)
                    mma_f16(acc[mi][ni], af, bf[ni]);
            }
        }

        if (s + 1 < 16) {
            stsA(s + 1);                 // into buf (s+1)&1 (free since end of s-1)
            if (s + 2 < 16) ldgA(s + 2); // prefetch, hides under next compute
        }
        __syncthreads();   // protect W/A16 buffer reuse at top of next iter
    }

    const float scale = (which == 0) ? 0.125f : 1.0f;
    __half* dst = (which == 0) ? g_q16 : g_k16;

#pragma unroll
    for (int mi = 0; mi < 4; mi++) {
        const int m1 = m0 + warp_m + mi * 16 + g;
        const int m2 = m1 + 8;
        const int s1 = m1 >> 1, b1 = m1 & 1;
        const int s2 = m2 >> 1, b2 = m2 & 1;
#pragma unroll
        for (int ni = 0; ni < 4; ni++) {
            const int n = n0 + warp_n + ni * 8 + tg * 2;
            const float bb0 = bias[n], bb1 = bias[n + 1];
            __half v00 = __float2half_rn((acc[mi][ni][0] + bb0) * scale);
            __half v01 = __float2half_rn((acc[mi][ni][1] + bb1) * scale);
            __half v10 = __float2half_rn((acc[mi][ni][2] + bb0) * scale);
            __half v11 = __float2half_rn((acc[mi][ni][3] + bb1) * scale);
            const int nl = n & 1023;
            const int h  = nl >> 6;
            const int d  = nl & 63;
            if (which < 2) {
                size_t base1 = (((size_t)(b1 * HH + h) * SQ + s1) * DD) + d;
                size_t base2 = (((size_t)(b2 * HH + h) * SQ + s2) * DD) + d;
                *(uint32_t*)&dst[base1] = pkh(v00, v01);
                *(uint32_t*)&dst[base2] = pkh(v10, v11);
            } else {
                size_t r1 = ((size_t)(b1 * HH + h) * DD + d) * SQ;
                size_t r2 = ((size_t)(b2 * HH + h) * DD + d) * SQ;
                g_v16t[r1 + s1]      = v00;
                g_v16t[r1 + SQ + s1] = v01;
                g_v16t[r2 + s2]      = v10;
                g_v16t[r2 + SQ + s2] = v11;
            }
        }
    }
}

// ---------------------------------------------------------------------------
// Banded flash attention, fp16, register-resident P, double-buffered K/V.
// (r10 verbatim)
// ---------------------------------------------------------------------------
__global__ __launch_bounds__(256, 2) void attn_kernel()
{
    extern __shared__ __align__(16) char smA[];
    const uint32_t sb = smem_u32(smA);

    const int t   = blockIdx.x;
    const int bh  = blockIdx.y;
    const int tid = threadIdx.x;
    const int w    = tid >> 5;
    const int lane = tid & 31;
    const int g    = lane >> 2;
    const int tg   = lane & 3;

    const int a_row   = (lane & 7) + ((lane >> 3) & 1) * 8;
    const int a_chunk = lane >> 4;
    const int b_row   = lane & 7;
    const int b_sel   = lane >> 4;
    const int b_chunk = (lane >> 3) & 1;

    const uint32_t q_lane = sb + (uint32_t)((w * 16 + a_row) * 144 + a_chunk * 16);
    const uint32_t k_lane = sb + 18432u + (uint32_t)((b_sel * 8 + b_row) * 144 + b_chunk * 16);
    const uint32_t v_lane = sb + 36864u + (uint32_t)((b_sel * 8 + b_row) * 272 + b_chunk * 16);

    auto issue_kv = [&](int kt, int buf) {
        const __half* kp = g_k16 + ((size_t)bh * SQ + kt * 128) * DD;
        const __half* vp = g_v16t + (size_t)bh * DD * SQ + kt * 128;
        const uint32_t kb = sb + 18432u + (uint32_t)buf * 35840u;
        const uint32_t vb = sb + 36864u + (uint32_t)buf * 35840u;
#pragma unroll
        for (int u = 0; u < 8; u++) {
            int ch = tid + u * 256;
            if (ch < 1024) {
                int kr = ch >> 3, kc = ch & 7;
                CP_ASYNC16(kb + (uint32_t)kr * 144u + (uint32_t)kc * 16u,
                           kp + kr * DD + kc * 8);
            } else {
                int vi = ch - 1024;
                int vr = vi >> 4, vc = vi & 15;
                CP_ASYNC16(vb + (uint32_t)vr * 272u + (uint32_t)vc * 16u,
                           vp + (size_t)vr * SQ + vc * 8);
            }
        }
        CP_COMMIT();
    };

    const int kt0 = (t > 0) ? t - 1 : t;
    const int kt1 = (t < SQ / 128 - 1) ? t + 1 : t;
    const int nkt = kt1 - kt0 + 1;

    {
        const __half* qp = g_q16 + ((size_t)bh * SQ + t * 128) * DD;
#pragma unroll
        for (int u = 0; u < 4; u++) {
            int ch = tid + u * 256;
            int row = ch >> 3, c = ch & 7;
            CP_ASYNC16(sb + (uint32_t)row * 144u + (uint32_t)c * 16u, qp + row * DD + c * 8);
        }
        CP_COMMIT();
    }
    issue_kv(kt0, 0);

    float l0 = 0.f, l1 = 0.f;
    float O[8][4];
#pragma unroll
    for (int nf = 0; nf < 8; nf++)
#pragma unroll
        for (int r = 0; r < 4; r++) O[nf][r] = 0.f;

    uint32_t qf[4][4];
    uint32_t Pf[8][4];
    bool qloaded = false;

#pragma unroll 1
    for (int it = 0; it < nkt; it++) {
        const int kt = kt0 + it;
        if (it + 1 < nkt) { issue_kv(kt + 1, (it + 1) & 1); CP_WAIT(1); }
        else              { CP_WAIT(0); }
        __syncthreads();

        if (!qloaded) {
            qloaded = true;
#pragma unroll
            for (int ks = 0; ks < 4; ks++)
                ldsm_x4(qf[ks], q_lane + ks * 32);
        }

        const uint32_t bufo = (uint32_t)(it & 1) * 35840u;
        const int dt = kt - t;
        const int niLo = (dt < 0) ? 2 * w : 0;
        const int niHi = (dt > 0) ? 2 * w + 2 : 16;
        const int r0 = w * 16 + g;
        const int r1 = r0 + 8;

#pragma unroll
        for (int ni = 0; ni < 16; ni += 2) {
            if (ni >= niLo && ni < niHi) {
                float c0[4] = {0.f, 0.f, 0.f, 0.f};
                float c1[4] = {0.f, 0.f, 0.f, 0.f};
                const uint32_t kb = k_lane + bufo + (uint32_t)ni * 1152u;
#pragma unroll
                for (int ks = 0; ks < 4; ks++) {
                    uint32_t r[4];
                    ldsm_x4(r, kb + ks * 32);
                    mma_f16(c0, qf[ks], r);
                    mma_f16(c1, qf[ks], r + 2);
                }
#pragma unroll
                for (int q2 = 0; q2 < 2; q2++) {
                    float* c = (q2 == 0) ? c0 : c1;
                    const int col0 = (ni + q2) * 8 + 2 * tg;
                    float p0, p1, p2, p3;
                    if (dt < 0) {
                        p0 = (col0     >= r0) ? __expf(c[0] - SHIFT) : 0.f;
                        p1 = (col0 + 1 >= r0) ? __expf(c[1] - SHIFT) : 0.f;
                        p2 = (col0     >= r1) ? __expf(c[2] - SHIFT) : 0.f;
                        p3 = (col0 + 1 >= r1) ? __expf(c[3] - SHIFT) : 0.f;
                    } else if (dt > 0) {
                        p0 = (col0     < r0) ? __expf(c[0] - SHIFT) : 0.f;
                        p1 = (col0 + 1 < r0) ? __expf(c[1] - SHIFT) : 0.f;
                        p2 = (col0     < r1) ? __expf(c[2] - SHIFT) : 0.f;
                        p3 = (col0 + 1 < r1) ? __expf(c[3] - SHIFT) : 0.f;
                    } else {
                        p0 = __expf(c[0] - SHIFT); p1 = __expf(c[1] - SHIFT);
                        p2 = __expf(c[2] - SHIFT); p3 = __expf(c[3] - SHIFT);
                    }
                    l0 += p0 + p1;
                    l1 += p2 + p3;
                    const int ck = (ni + q2) >> 1;
                    if (((ni + q2) & 1) == 0) {
                        Pf[ck][0] = cvt2(p0, p1);
                        Pf[ck][1] = cvt2(p2, p3);
                    } else {
                        Pf[ck][2] = cvt2(p0, p1);
                        Pf[ck][3] = cvt2(p2, p3);
                    }
                }
            }
        }

        const int ksLo = (dt < 0) ? w : 0;
        const int ksHi = (dt > 0) ? w + 1 : 8;
#pragma unroll
        for (int ks = 0; ks < 8; ks++) {
            if (ks >= ksLo && ks < ksHi) {
#pragma unroll
                for (int nf = 0; nf < 8; nf += 2) {
                    uint32_t v[4];
                    ldsm_x4(v, v_lane + bufo + (uint32_t)nf * 2176u + ks * 32);
                    mma_f16(O[nf],     Pf[ks], v);
                    mma_f16(O[nf + 1], Pf[ks], v + 2);
                }
            }
        }
        if (it + 1 < nkt) __syncthreads();
    }

    l0 += __shfl_xor_sync(0xffffffff, l0, 1);
    l0 += __shfl_xor_sync(0xffffffff, l0, 2);
    l1 += __shfl_xor_sync(0xffffffff, l1, 1);
    l1 += __shfl_xor_sync(0xffffffff, l1, 2);
    const float inv0 = 1.0f / l0;
    const float inv1 = 1.0f / l1;

    const int b_ = bh >> 4;
    const int h_ = bh & 15;
    const int i0 = t * 128 + w * 16 + g;
    const int i1 = i0 + 8;
#pragma unroll
    for (int nf = 0; nf < 8; nf++) {
        const int d = h_ * 64 + nf * 8 + 2 * tg;
        size_t e0 = ((size_t)i0 * BB + b_) * EE + d;
        size_t e1 = ((size_t)i1 * BB + b_) * EE + d;
        *(uint32_t*)&g_c16[e0] = cvt2(O[nf][0] * inv0, O[nf][1] * inv0);
        *(uint32_t*)&g_c16[e1] = cvt2(O[nf][2] * inv1, O[nf][3] * inv1);
    }
}

// ---------------------------------------------------------------------------
// Output projection, fp16 single-pass (r10 verbatim).
// ---------------------------------------------------------------------------
__global__ __launch_bounds__(256, 2) void outproj_kernel(
    const float* __restrict__ bias, float* __restrict__ outp)
{
    extern __shared__ __align__(16) char smB[];
    const uint32_t sb = smem_u32(smB);
    const int tid  = threadIdx.x;
    const int wid  = tid >> 5;
    const int lane = tid & 31;
    const int g    = lane >> 2;
    const int tg   = lane & 3;
    const int m0 = blockIdx.x * 128;
    const int n0 = blockIdx.y * 128;

    const int warp_m = (wid & 1) * 64;
    const int warp_n = (wid >> 1) * 32;

    const int a_row   = (lane & 7) + ((lane >> 3) & 1) * 8;
    const int a_chunk = lane >> 4;
    const int b_row   = lane & 7;
    const int b_sel   = lane >> 4;
    const int b_chunk = (lane >> 3) & 1;

    const uint32_t a_lane = (uint32_t)((warp_m + a_row) * 144 + a_chunk * 16);
    const uint32_t b_lane = 18432u + (uint32_t)((warp_n + b_sel * 8 + b_row) * 144 + b_chunk * 16);

    float acc[4][4][4];
#pragma unroll
    for (int mi = 0; mi < 4; mi++)
#pragma unroll
        for (int ni = 0; ni < 4; ni++)
#pragma unroll
            for (int r = 0; r < 4; r++) acc[mi][ni][r] = 0.0f;

    auto issue_stage = [&](int s) {
        const int k0 = s * 64;
        const uint32_t base = sb + (uint32_t)(s & 1) * 36864u;
#pragma unroll
        for (int u = 0; u < 8; u++) {
            int ch  = tid + u * 256;
            int arr = ch >> 10;
            int rem = ch & 1023;
            int row = rem >> 3;
            int c   = rem & 7;
            uint32_t so = (uint32_t)arr * 18432u + (uint32_t)row * 144u + (uint32_t)c * 16u;
            const __half* gp = (arr == 0)
                ? g_c16  + (size_t)(m0 + row) * EE + k0 + c * 8
                : g_wo16 + (size_t)(n0 + row) * EE + k0 + c * 8;
            CP_ASYNC16(base + so, gp);
        }
        CP_COMMIT();
    };

    issue_stage(0);

    for (int s = 0; s < 16; s++) {
        if (s + 1 < 16) { issue_stage(s + 1); CP_WAIT(1); }
        else            { CP_WAIT(0); }
        __syncthreads();

        const uint32_t stb = sb + (uint32_t)(s & 1) * 36864u;
#pragma unroll
        for (int ks = 0; ks < 4; ks++) {
            uint32_t bf[4][2];
#pragma unroll
            for (int np = 0; np < 2; np++) {
                uint32_t r[4];
                ldsm_x4(r, stb + b_lane + (uint32_t)np * 2304u + ks * 32);
                bf[np * 2][0] = r[0];     bf[np * 2][1] = r[1];
                bf[np * 2 + 1][0] = r[2]; bf[np * 2 + 1][1] = r[3];
            }
#pragma unroll
            for (int mi = 0; mi < 4; mi++) {
                uint32_t af[4];
                ldsm_x4(af, stb + a_lane + (uint32_t)mi * 2304u + ks * 32);
#pragma unroll
                for (int ni = 0; ni < 4; ni++)
                    mma_f16(acc[mi][ni], af, bf[ni]);
            }
        }
        __syncthreads();
    }

#pragma unroll
    for (int mi = 0; mi < 4; mi++) {
        const int m1 = m0 + warp_m + mi * 16 + g;
        const int m2 = m1 + 8;
#pragma unroll
        for (int ni = 0; ni < 4; ni++) {
            const int n = n0 + warp_n + ni * 8 + tg * 2;
            const float b0 = bias[n], b1 = bias[n + 1];
            *(float2*)&outp[(size_t)m1 * EE + n] =
                make_float2(acc[mi][ni][0] + b0, acc[mi][ni][1] + b1);
            *(float2*)&outp[(size_t)m2 * EE + n] =
                make_float2(acc[mi][ni][2] + b0, acc[mi][ni][3] + b1);
        }
    }
}

// ---------------------------------------------------------------------------
extern "C" void kernel_launch(void* const* d_in, const int* in_sizes, int n_in,
                              void* d_out, int out_size)
{
    const float* q_in  = (const float*)d_in[0];
    const float* k_in  = (const float*)d_in[1];
    const float* v_in  = (const float*)d_in[2];
    const float* w_in  = (const float*)d_in[3];
    const float* b_in  = (const float*)d_in[4];
    const float* w_out = (const float*)d_in[5];
    const float* b_out = (const float*)d_in[6];
    float* out = (float*)d_out;

    // Weights-only conversion (w + wo)
    cvt_w_kernel<<<NWALL4 / 1024, 256>>>((const float4*)w_in, (const float4*)w_out);

    // QKV projection (fp16, in-register A conversion), grid 32 x 24
    const int qkv_smem = 73728;
    cudaFuncSetAttribute(qkv_gemm_kernel, cudaFuncAttributeMaxDynamicSharedMemorySize, qkv_smem);
    qkv_gemm_kernel<<<dim3(MM / 128, (3 * EE) / 128), 256, qkv_smem>>>(
        q_in, k_in, v_in, b_in);

    // Banded attention (register-P fp16, double-buffered K/V)
    const int attn_smem = 90112;
    cudaFuncSetAttribute(attn_kernel, cudaFuncAttributeMaxDynamicSharedMemorySize, attn_smem);
    attn_kernel<<<dim3(SQ / 128, BB * HH), 256, attn_smem>>>();

    // Output projection (fp16 single-pass), grid 32 x 8
    const int op_smem = 73728;
    cudaFuncSetAttribute(outproj_kernel, cudaFuncAttributeMaxDynamicSharedMemorySize, op_smem);
    outproj_kernel<<<dim3(MM / 128, EE / 128), 256, op_smem>>>(b_out, out);
}